// round 15
// baseline (speedup 1.0000x reference)
#include <cuda_runtime.h>
#include <cuda_fp16.h>
#include <math.h>
#include <stdint.h>

#define D   64
#define C3  192
#define MAXN 100352
#define MAXE 1600064

// ---------------- device scratch (static, no allocation) ----------------
__device__ float d_xA[MAXN * D];
__device__ float d_xB[MAXN * D];
__device__ int   d_indeg[MAXN];
__device__ int   d_off  [MAXN];
__device__ int   d_cur  [MAXN];
__device__ int   d_csrc [MAXE];
// Packed fp16 B per layer l=0..2 (global 2..4): [k=0..63][col'=0..383]
// col' = w*48 + j*8 + t : warp w owns dims 8w..8w+7; j=0..2 gi gates (r,z,n), j=3..5 gh gates
__device__ __align__(16) __half d_Bk[3][64][384];
__device__ float d_q[C3], d_p2[C3], d_x1row[D];
__device__ float d_pool[64 * D];
__device__ int   d_gstart[66];

__device__ __forceinline__ float sigf(float x) { return 1.0f / (1.0f + expf(-x)); }

__device__ __forceinline__ uint32_t smem_u32(const void* p) {
    uint32_t a;
    asm("{ .reg .u64 t; cvta.to.shared.u64 t, %1; cvt.u32.u64 %0, t; }" : "=r"(a) : "l"(p));
    return a;
}
__device__ __forceinline__ void ldmA4(uint32_t a[4], uint32_t addr) {
    asm volatile("ldmatrix.sync.aligned.m8n8.x4.shared.b16 {%0,%1,%2,%3}, [%4];"
                 : "=r"(a[0]), "=r"(a[1]), "=r"(a[2]), "=r"(a[3]) : "r"(addr));
}
__device__ __forceinline__ void ldmB2(uint32_t b[2], uint32_t addr) {
    asm volatile("ldmatrix.sync.aligned.m8n8.x2.trans.shared.b16 {%0,%1}, [%2];"
                 : "=r"(b[0]), "=r"(b[1]) : "r"(addr));
}
__device__ __forceinline__ void mma16816(float c[4], const uint32_t a[4], const uint32_t b[2]) {
    asm volatile("mma.sync.aligned.m16n8k16.row.col.f32.f16.f16.f32 "
                 "{%0,%1,%2,%3}, {%4,%5,%6,%7}, {%8,%9}, {%0,%1,%2,%3};"
                 : "+f"(c[0]), "+f"(c[1]), "+f"(c[2]), "+f"(c[3])
                 : "r"(a[0]), "r"(a[1]), "r"(a[2]), "r"(a[3]), "r"(b[0]), "r"(b[1]));
}

// ---------------- CSR build ----------------
__global__ void k_init(int N, int G) {
    int i = blockIdx.x * blockDim.x + threadIdx.x;
    if (i < N) d_indeg[i] = 0;
    if (i <= G + 1) d_gstart[i] = N;
}

// edge counting + graph boundary detection (batch is sorted)
__global__ void k_count(const int* __restrict__ ei, const int* __restrict__ batch,
                        int E, int N) {
    int i = blockIdx.x * blockDim.x + threadIdx.x;
    if (i < E) atomicAdd(&d_indeg[ei[E + i]], 1);
    if (i < N) {
        if (i == 0) d_gstart[batch[0]] = 0;
        else if (batch[i] != batch[i - 1]) d_gstart[batch[i]] = i;
    }
}

__global__ void k_scan(int N) {
    __shared__ int sm[1024];
    int t = threadIdx.x;
    int chunk = (N + 1023) >> 10;
    int b = t * chunk, e = min(N, b + chunk);
    int s = 0;
    for (int i = b; i < e; i++) s += d_indeg[i];
    sm[t] = s;
    __syncthreads();
    for (int off = 1; off < 1024; off <<= 1) {
        int v = (t >= off) ? sm[t - off] : 0;
        __syncthreads();
        sm[t] += v;
        __syncthreads();
    }
    int run = sm[t] - s;
    for (int i = b; i < e; i++) {
        d_off[i] = run;
        d_cur[i] = run;
        run += d_indeg[i];
    }
}

__global__ void k_fill(const int* __restrict__ ei, int E) {
    int i = blockIdx.x * blockDim.x + threadIdx.x;
    if (i < E) {
        int s = ei[i];
        int d = ei[E + i];
        int p = atomicAdd(&d_cur[d], 1);
        d_csrc[p] = s;
    }
}

__global__ void k_gfix(int G, int N) {
    d_gstart[G] = N;
    for (int g = G - 1; g >= 0; g--)
        if (d_gstart[g] > d_gstart[g + 1]) d_gstart[g] = d_gstart[g + 1];
}

// ---------------- layers 1+2 analytic shortcuts ----------------
__global__ void k_const(const float* __restrict__ convw,
                        const float* __restrict__ wih,
                        const float* __restrict__ whh,
                        const float* __restrict__ bih,
                        const float* __restrict__ bhh) {
    __shared__ float x1[D], m2[D];
    int t = threadIdx.x;
    if (t < D) {
        float r = sigf(bih[t] + bhh[t]);
        float z = sigf(bih[64 + t] + bhh[64 + t]);
        float n = tanhf(bih[128 + t] + r * bhh[128 + t]);
        x1[t] = (1.0f - z) * n;
    }
    __syncthreads();
    if (t < D) {
        const float* w1 = convw + 1 * D * D;
        float s = 0.0f;
        for (int k = 0; k < D; k++) s += x1[k] * w1[k * D + t];
        m2[t] = s;
        d_x1row[t] = x1[t];
    }
    __syncthreads();
    if (t < C3) {
        const float* wih1 = wih + 1 * C3 * D;
        const float* whh1 = whh + 1 * C3 * D;
        const float* bhh1 = bhh + 1 * C3;
        float sq = 0.0f, sp = 0.0f;
        for (int j = 0; j < D; j++) {
            sq += m2[j] * wih1[t * D + j];
            sp += x1[j] * whh1[t * D + j];
        }
        d_q[t]  = sq;
        d_p2[t] = sp + bhh1[t];
    }
}

__global__ void k_layer2(const float* __restrict__ bih1, int N) {
    int idx = blockIdx.x * blockDim.x + threadIdx.x;
    if (idx >= N * D) return;
    int v = idx >> 6, d = idx & 63;
    float deg = (float)d_indeg[v];
    float r = sigf(deg * d_q[d]       + bih1[d]       + d_p2[d]);
    float z = sigf(deg * d_q[64 + d]  + bih1[64 + d]  + d_p2[64 + d]);
    float n = tanhf(deg * d_q[128 + d] + bih1[128 + d] + r * d_p2[128 + d]);
    d_xA[idx] = (1.0f - z) * n + z * d_x1row[d];
}

// ---------------- pre-pack fp16 B, gate-interleaved cols ----------------
__global__ void k_bprep(const float* __restrict__ convw,
                        const float* __restrict__ wih,
                        const float* __restrict__ whh) {
    int idx = blockIdx.x * blockDim.x + threadIdx.x;  // 3*2*192*64
    if (idx >= 73728) return;
    int l0 = idx / 24576;
    int rem = idx % 24576;
    int m = rem / 12288;
    int rem2 = rem % 12288;
    int c = rem2 >> 6;      // 0..191 (gate*64 + d)
    int k = rem2 & 63;
    int lg = l0 + 2;
    float val;
    if (m == 0) {
        const float* w  = convw + lg * D * D + k * D;
        const float* wi = wih   + lg * C3 * D + c * D;
        float s = 0.0f;
        for (int j = 0; j < D; j++) s += w[j] * wi[j];
        val = s;
    } else {
        val = whh[lg * C3 * D + c * D + k];
    }
    int gate = c >> 6, d = c & 63;
    int w8 = d >> 3, t = d & 7;
    int jj = (m == 0) ? gate : gate + 3;
    int col = w8 * 48 + jj * 8 + t;
    d_Bk[l0][k][col] = __float2half_rn(val);
}

// ---------------- fused layer: gather phase + HMMA+GRU phase ----------------
// 256 threads = 8 warps, 64-node tiles, 2 blocks/SM for cross-block phase overlap.
// Warp w owns dims 8w..8w+7 (cols w*48..+47), both 32-row chunks.
// A: S = Sh single term, X = Xh single term (B-fp16 error dominates; calibrated budget).
#define BP 392            // B smem pitch (halves): 784B
#define AP 72             // A smem pitch (halves): 144B
#define SM_B    0
#define SM_BUF  50176
#define OF_SHI 0
#define OF_XHI 9216
#define SM_TOT  (50176 + 18432)

__global__ void __launch_bounds__(256, 2) k_layer(int cur, int l, int N,
                                                  const float* __restrict__ bih,
                                                  const float* __restrict__ bhh) {
    extern __shared__ char smem[];
    uint32_t sb = smem_u32(smem);
    int tid = threadIdx.x, wid = tid >> 5, lane = tid & 31;
    const float* Xin  = cur ? d_xB : d_xA;
    float*       Xout = cur ? d_xA : d_xB;
    char* buf = smem + SM_BUF;

    // ---- load resident B (fp16), pitch BP ----
    {
        const int4* src = (const int4*)(&d_Bk[l][0][0]);
        for (int i = tid; i < 3072; i += 256) {
            int row = i / 48, cb = i % 48;
            *(int4*)(smem + SM_B + row * (BP * 2) + cb * 16) = src[i];
        }
    }

    // consumer setup
    uint32_t aoff = (uint32_t)(lane & 15) * (AP * 2) + ((lane >> 4) << 3) * 2;
    uint32_t boff = (uint32_t)(lane & 15) * (BP * 2);
    int wcol = wid * 48;
    int gID = lane >> 2, tig = lane & 3;
    int d0 = wid * 8 + 2 * tig;
    float bir0 = __ldg(&bih[d0]),        bir1 = __ldg(&bih[d0 + 1]);
    float biz0 = __ldg(&bih[64 + d0]),   biz1 = __ldg(&bih[64 + d0 + 1]);
    float bin0 = __ldg(&bih[128 + d0]),  bin1 = __ldg(&bih[128 + d0 + 1]);
    float bhr0 = __ldg(&bhh[d0]),        bhr1 = __ldg(&bhh[d0 + 1]);
    float bhz0 = __ldg(&bhh[64 + d0]),   bhz1 = __ldg(&bhh[64 + d0 + 1]);
    float bhn0 = __ldg(&bhh[128 + d0]),  bhn1 = __ldg(&bhh[128 + d0 + 1]);

    int ntiles = (N + 63) >> 6;
    for (int t = blockIdx.x; t < ntiles; t += gridDim.x) {
        int n0 = t << 6;
        __syncthreads();   // previous tile's MMA reads complete before overwrite

        // ---- phase 1: gather + fp16 convert, 8 warps x 8 nodes ----
        #pragma unroll 1
        for (int nn = 0; nn < 8; nn++) {
            int node = wid * 8 + nn;
            int gn = n0 + node;
            float2 sa = make_float2(0.f, 0.f);
            float2 xv = make_float2(0.f, 0.f);
            if (gn < N) {
                int o = d_off[gn], dg = d_indeg[gn];
                float2 a0 = make_float2(0.f, 0.f), a1 = make_float2(0.f, 0.f);
                float2 a2 = make_float2(0.f, 0.f), a3 = make_float2(0.f, 0.f);
                int e = 0;
                for (; e + 3 < dg; e += 4) {
                    int u0 = d_csrc[o + e],     u1 = d_csrc[o + e + 1];
                    int u2 = d_csrc[o + e + 2], u3 = d_csrc[o + e + 3];
                    float2 v0 = ((const float2*)(Xin + u0 * 64))[lane];
                    float2 v1 = ((const float2*)(Xin + u1 * 64))[lane];
                    float2 v2 = ((const float2*)(Xin + u2 * 64))[lane];
                    float2 v3 = ((const float2*)(Xin + u3 * 64))[lane];
                    a0.x += v0.x; a0.y += v0.y;
                    a1.x += v1.x; a1.y += v1.y;
                    a2.x += v2.x; a2.y += v2.y;
                    a3.x += v3.x; a3.y += v3.y;
                }
                for (; e < dg; e++) {
                    int u = d_csrc[o + e];
                    float2 v = ((const float2*)(Xin + u * 64))[lane];
                    a0.x += v.x; a0.y += v.y;
                }
                sa.x = (a0.x + a1.x) + (a2.x + a3.x);
                sa.y = (a0.y + a1.y) + (a2.y + a3.y);
                xv = ((const float2*)(Xin + gn * 64))[lane];
            }
            __half2 sh = __float22half2_rn(sa);
            __half2 xh = __float22half2_rn(xv);
            uint32_t off = (uint32_t)node * (AP * 2) + lane * 4;
            *(uint32_t*)(buf + OF_SHI + off) = *(uint32_t*)&sh;
            *(uint32_t*)(buf + OF_XHI + off) = *(uint32_t*)&xh;
        }
        __syncthreads();

        // ---- phase 2: MMA + register GRU (each warp: both 32-row chunks) ----
        uint32_t bufa = sb + SM_BUF;
        #pragma unroll
        for (int mi = 0; mi < 2; mi++) {
            int m0 = mi * 32;
            float c[2][6][4];
            #pragma unroll
            for (int mf = 0; mf < 2; mf++)
                #pragma unroll
                for (int j = 0; j < 6; j++)
                    #pragma unroll
                    for (int q = 0; q < 4; q++) c[mf][j][q] = 0.0f;

            #pragma unroll
            for (int ks = 0; ks < 4; ks++) {
                int k0 = ks * 16;
                uint32_t abase = (uint32_t)m0 * (AP * 2) + k0 * 2 + aoff;
                uint32_t sh[2][4], xh[2][4];
                ldmA4(sh[0], bufa + OF_SHI + abase);
                ldmA4(sh[1], bufa + OF_SHI + abase + 16 * (AP * 2));
                ldmA4(xh[0], bufa + OF_XHI + abase);
                ldmA4(xh[1], bufa + OF_XHI + abase + 16 * (AP * 2));
                #pragma unroll
                for (int j = 0; j < 6; j++) {
                    uint32_t bh[2];
                    uint32_t bbase = (uint32_t)k0 * (BP * 2) + (wcol + 8 * j) * 2 + boff;
                    ldmB2(bh, sb + SM_B + bbase);
                    if (j < 3) {
                        mma16816(c[0][j], sh[0], bh);
                        mma16816(c[1][j], sh[1], bh);
                    } else {
                        mma16816(c[0][j], xh[0], bh);
                        mma16816(c[1][j], xh[1], bh);
                    }
                }
            }

            // register GRU epilogue for this 32-node chunk
            #pragma unroll
            for (int mf = 0; mf < 2; mf++) {
                #pragma unroll
                for (int half = 0; half < 2; half++) {
                    int r = m0 + mf * 16 + gID + half * 8;
                    int node = n0 + r;
                    if (node < N) {
                        int q0 = half * 2, q1 = q0 + 1;
                        float2 xi = __ldg(((const float2*)(Xin + node * 64)) + (d0 >> 1));
                        float rr0 = sigf(c[mf][0][q0] + bir0 + c[mf][3][q0] + bhr0);
                        float zz0 = sigf(c[mf][1][q0] + biz0 + c[mf][4][q0] + bhz0);
                        float nn0 = tanhf(c[mf][2][q0] + bin0 + rr0 * (c[mf][5][q0] + bhn0));
                        float o0 = (1.0f - zz0) * nn0 + zz0 * xi.x;
                        float rr1 = sigf(c[mf][0][q1] + bir1 + c[mf][3][q1] + bhr1);
                        float zz1 = sigf(c[mf][1][q1] + biz1 + c[mf][4][q1] + bhz1);
                        float nn1 = tanhf(c[mf][2][q1] + bin1 + rr1 * (c[mf][5][q1] + bhn1));
                        float o1 = (1.0f - zz1) * nn1 + zz1 * xi.y;
                        ((float2*)(Xout + node * 64))[d0 >> 1] = make_float2(o0, o1);
                    }
                }
            }
        }
    }
}

// ---------------- segmented pooling (batch is sorted) ----------------
__global__ void k_pool2(int cur, int N) {
    __shared__ float red[256];
    const float* x = cur ? d_xB : d_xA;
    int g = blockIdx.x;
    int t = threadIdx.x;
    int d = t & 63, part = t >> 6;
    int s = d_gstart[g], e = d_gstart[g + 1];
    float acc = 0.0f;
    for (int n = s + part; n < e; n += 4) acc += x[n * D + d];
    red[t] = acc;
    __syncthreads();
    if (t < 64)
        d_pool[g * D + t] = red[t] + red[64 + t] + red[128 + t] + red[192 + t];
}

__global__ void k_mlp(const float* __restrict__ w1, const float* __restrict__ b1,
                      const float* __restrict__ w2, const float* __restrict__ b2,
                      const float* __restrict__ w3, const float* __restrict__ b3,
                      float* __restrict__ out) {
    __shared__ float h1[32], h2[16];
    int g = blockIdx.x, t = threadIdx.x;
    if (t < 32) {
        float s = b1[t];
        for (int k = 0; k < D; k++) s += d_pool[g * D + k] * w1[t * D + k];
        h1[t] = (s > 0.0f) ? s : expm1f(s);
    }
    __syncthreads();
    if (t < 16) {
        float s = b2[t];
        for (int k = 0; k < 32; k++) s += h1[k] * w2[t * 32 + k];
        h2[t] = (s > 0.0f) ? s : expm1f(s);
    }
    __syncthreads();
    if (t == 0) {
        float s = b3[0];
        for (int k = 0; k < 16; k++) s += h2[k] * w3[k];
        out[g] = s;
    }
}

// ---------------- launch ----------------
extern "C" void kernel_launch(void* const* d_in, const int* in_sizes, int n_in,
                              void* d_out, int out_size) {
    const float* convw = (const float*)d_in[0];
    const float* wih   = (const float*)d_in[1];
    const float* whh   = (const float*)d_in[2];
    const float* bih   = (const float*)d_in[3];
    const float* bhh   = (const float*)d_in[4];
    const float* fc1w  = (const float*)d_in[5];
    const float* fc1b  = (const float*)d_in[6];
    const float* fc2w  = (const float*)d_in[7];
    const float* fc2b  = (const float*)d_in[8];
    const float* fc3w  = (const float*)d_in[9];
    const float* fc3b  = (const float*)d_in[10];
    const int*   ei    = (const int*)d_in[11];
    const int*   batch = (const int*)d_in[12];

    int E = in_sizes[11] / 2;
    int N = in_sizes[12];
    int G = out_size;
    float* out = (float*)d_out;

    static int smem_set = 0;
    if (!smem_set) {
        cudaFuncSetAttribute(k_layer, cudaFuncAttributeMaxDynamicSharedMemorySize, SM_TOT);
        smem_set = 1;
    }

    int tb = 256;
    int gN    = (N + tb - 1) / tb;
    int gE    = (E + tb - 1) / tb;
    int gND   = (N * D + tb - 1) / tb;

    // CSR build + graph ranges
    k_init<<<gN, tb>>>(N, G);
    k_count<<<gE, tb>>>(ei, batch, E, N);
    k_scan<<<1, 1024>>>(N);
    k_fill<<<gE, tb>>>(ei, E);
    k_gfix<<<1, 1>>>(G, N);

    // analytic layers 1+2 and B packing
    k_const<<<1, 192>>>(convw, wih, whh, bih, bhh);
    k_layer2<<<gND, tb>>>(bih + C3, N);           // writes d_xA (cur=0)
    k_bprep<<<(73728 + tb - 1) / tb, tb>>>(convw, wih, whh);

    // layers 3..5: fused gather + HMMA + GRU, 2 blocks/SM phase overlap, ping-pong
    int cur = 0;
    for (int l = 0; l < 3; l++) {
        int lg = l + 2;
        k_layer<<<296, 256, SM_TOT>>>(cur, l, N, bih + lg * C3, bhh + lg * C3);
        cur ^= 1;
    }

    // pooling + MLP head
    k_pool2<<<G, 256>>>(cur, N);
    k_mlp<<<G, 64>>>(fc1w, fc1b, fc2w, fc2b, fc3w, fc3b, out);
}

// round 16
// speedup vs baseline: 1.9564x; 1.9564x over previous
#include <cuda_runtime.h>
#include <cuda_fp16.h>
#include <math.h>
#include <stdint.h>

#define D   64
#define C3  192
#define MAXN 100352
#define MAXE 1600064

// ---------------- device scratch (static, no allocation) ----------------
__device__ float d_xA[MAXN * D];
__device__ float d_xB[MAXN * D];
__device__ int   d_indeg[MAXN];
__device__ int   d_off  [MAXN];
__device__ int   d_cur  [MAXN];
__device__ int   d_csrc [MAXE];
__device__ int   d_csum [128];
// Packed fp16 B per layer l=0..2 (global 2..4): [k=0..63][col'=0..383]
// col' = w*48 + j*8 + t : warp w owns dims 8w..8w+7; j=0..2 gi gates (r,z,n), j=3..5 gh gates
__device__ __align__(16) __half d_Bk[3][64][384];
__device__ float d_q[C3], d_p2[C3], d_x1row[D];
__device__ float d_pool[64 * D];
__device__ int   d_gstart[66];

__device__ __forceinline__ float sigf(float x) { return 1.0f / (1.0f + expf(-x)); }

__device__ __forceinline__ uint32_t smem_u32(const void* p) {
    uint32_t a;
    asm("{ .reg .u64 t; cvta.to.shared.u64 t, %1; cvt.u32.u64 %0, t; }" : "=r"(a) : "l"(p));
    return a;
}
__device__ __forceinline__ void ldmA4(uint32_t a[4], uint32_t addr) {
    asm volatile("ldmatrix.sync.aligned.m8n8.x4.shared.b16 {%0,%1,%2,%3}, [%4];"
                 : "=r"(a[0]), "=r"(a[1]), "=r"(a[2]), "=r"(a[3]) : "r"(addr));
}
__device__ __forceinline__ void ldmB2(uint32_t b[2], uint32_t addr) {
    asm volatile("ldmatrix.sync.aligned.m8n8.x2.trans.shared.b16 {%0,%1}, [%2];"
                 : "=r"(b[0]), "=r"(b[1]) : "r"(addr));
}
__device__ __forceinline__ void mma16816(float c[4], const uint32_t a[4], const uint32_t b[2]) {
    asm volatile("mma.sync.aligned.m16n8k16.row.col.f32.f16.f16.f32 "
                 "{%0,%1,%2,%3}, {%4,%5,%6,%7}, {%8,%9}, {%0,%1,%2,%3};"
                 : "+f"(c[0]), "+f"(c[1]), "+f"(c[2]), "+f"(c[3])
                 : "r"(a[0]), "r"(a[1]), "r"(a[2]), "r"(a[3]), "r"(b[0]), "r"(b[1]));
}

// ---------------- CSR build ----------------
__global__ void k_init(int N, int G) {
    int i = blockIdx.x * blockDim.x + threadIdx.x;
    if (i < N) d_indeg[i] = 0;
    if (i <= G + 1) d_gstart[i] = N;
}

// edge counting + graph boundary detection (batch is sorted)
__global__ void k_count(const int* __restrict__ ei, const int* __restrict__ batch,
                        int E, int N) {
    int i = blockIdx.x * blockDim.x + threadIdx.x;
    if (i < E) atomicAdd(&d_indeg[ei[E + i]], 1);
    if (i < N) {
        if (i == 0) d_gstart[batch[0]] = 0;
        else if (batch[i] != batch[i - 1]) d_gstart[batch[i]] = i;
    }
}

// ---- parallel 3-phase exclusive scan over indegree ----
// phase A: per-chunk sums (chunk = 1024 elements)
__global__ void k_scanA(int N) {
    __shared__ int sm[256];
    int c = blockIdx.x, t = threadIdx.x;
    int base = c << 10;
    int s = 0;
    #pragma unroll
    for (int j = 0; j < 4; j++) {
        int i = base + t + j * 256;
        if (i < N) s += d_indeg[i];
    }
    sm[t] = s;
    __syncthreads();
    for (int off = 128; off > 0; off >>= 1) {
        if (t < off) sm[t] += sm[t + off];
        __syncthreads();
    }
    if (t == 0) d_csum[c] = sm[0];
}

// phase B: serial exclusive scan of chunk sums (tiny)
__global__ void k_scanB(int nchunks) {
    int run = 0;
    for (int c = 0; c < nchunks; c++) {
        int v = d_csum[c];
        d_csum[c] = run;
        run += v;
    }
}

// phase C: per-chunk local exclusive scan + chunk base
__global__ void k_scanC(int N) {
    __shared__ int sm[1024];
    int c = blockIdx.x, t = threadIdx.x;
    int i = (c << 10) + t;
    int v = (i < N) ? d_indeg[i] : 0;
    sm[t] = v;
    __syncthreads();
    for (int off = 1; off < 1024; off <<= 1) {
        int u = (t >= off) ? sm[t - off] : 0;
        __syncthreads();
        sm[t] += u;
        __syncthreads();
    }
    if (i < N) {
        int excl = d_csum[c] + sm[t] - v;
        d_off[i] = excl;
        d_cur[i] = excl;
    }
}

__global__ void k_fill(const int* __restrict__ ei, int E) {
    int i = blockIdx.x * blockDim.x + threadIdx.x;
    if (i < E) {
        int s = ei[i];
        int d = ei[E + i];
        int p = atomicAdd(&d_cur[d], 1);
        d_csrc[p] = s;
    }
}

__global__ void k_gfix(int G, int N) {
    d_gstart[G] = N;
    for (int g = G - 1; g >= 0; g--)
        if (d_gstart[g] > d_gstart[g + 1]) d_gstart[g] = d_gstart[g + 1];
}

// ---------------- layers 1+2 analytic shortcuts ----------------
__global__ void k_const(const float* __restrict__ convw,
                        const float* __restrict__ wih,
                        const float* __restrict__ whh,
                        const float* __restrict__ bih,
                        const float* __restrict__ bhh) {
    __shared__ float x1[D], m2[D];
    int t = threadIdx.x;
    if (t < D) {
        float r = sigf(bih[t] + bhh[t]);
        float z = sigf(bih[64 + t] + bhh[64 + t]);
        float n = tanhf(bih[128 + t] + r * bhh[128 + t]);
        x1[t] = (1.0f - z) * n;
    }
    __syncthreads();
    if (t < D) {
        const float* w1 = convw + 1 * D * D;
        float s = 0.0f;
        for (int k = 0; k < D; k++) s += x1[k] * w1[k * D + t];
        m2[t] = s;
        d_x1row[t] = x1[t];
    }
    __syncthreads();
    if (t < C3) {
        const float* wih1 = wih + 1 * C3 * D;
        const float* whh1 = whh + 1 * C3 * D;
        const float* bhh1 = bhh + 1 * C3;
        float sq = 0.0f, sp = 0.0f;
        for (int j = 0; j < D; j++) {
            sq += m2[j] * wih1[t * D + j];
            sp += x1[j] * whh1[t * D + j];
        }
        d_q[t]  = sq;
        d_p2[t] = sp + bhh1[t];
    }
}

__global__ void k_layer2(const float* __restrict__ bih1, int N) {
    int idx = blockIdx.x * blockDim.x + threadIdx.x;
    if (idx >= N * D) return;
    int v = idx >> 6, d = idx & 63;
    float deg = (float)d_indeg[v];
    float r = sigf(deg * d_q[d]       + bih1[d]       + d_p2[d]);
    float z = sigf(deg * d_q[64 + d]  + bih1[64 + d]  + d_p2[64 + d]);
    float n = tanhf(deg * d_q[128 + d] + bih1[128 + d] + r * d_p2[128 + d]);
    d_xA[idx] = (1.0f - z) * n + z * d_x1row[d];
}

// ---------------- pre-pack fp16 B, gate-interleaved cols ----------------
__global__ void k_bprep(const float* __restrict__ convw,
                        const float* __restrict__ wih,
                        const float* __restrict__ whh) {
    int idx = blockIdx.x * blockDim.x + threadIdx.x;  // 3*2*192*64
    if (idx >= 73728) return;
    int l0 = idx / 24576;
    int rem = idx % 24576;
    int m = rem / 12288;
    int rem2 = rem % 12288;
    int c = rem2 >> 6;      // 0..191 (gate*64 + d)
    int k = rem2 & 63;
    int lg = l0 + 2;
    float val;
    if (m == 0) {
        const float* w  = convw + lg * D * D + k * D;
        const float* wi = wih   + lg * C3 * D + c * D;
        float s = 0.0f;
        for (int j = 0; j < D; j++) s += w[j] * wi[j];
        val = s;
    } else {
        val = whh[lg * C3 * D + c * D + k];
    }
    int gate = c >> 6, d = c & 63;
    int w8 = d >> 3, t = d & 7;
    int jj = (m == 0) ? gate : gate + 3;
    int col = w8 * 48 + jj * 8 + t;
    d_Bk[l0][k][col] = __float2half_rn(val);
}

// ---------------- fused layer: gather phase + HMMA+GRU phase ----------------
// 256 threads = 8 warps, 64-node tiles, 2 blocks/SM for cross-block phase overlap.
// Warp w owns dims 8w..8w+7 (cols w*48..+47), both 32-row chunks.
// A split: S = Sh+Sl (2 terms), X = Xh only (1 term).  [R13 known-good config]
#define BP 392            // B smem pitch (halves): 784B
#define AP 72             // A smem pitch (halves): 144B
#define SM_B    0
#define SM_BUF  50176
#define OF_SHI 0
#define OF_SLO 9216
#define OF_XHI 18432
#define SM_TOT  (50176 + 27648)

__global__ void __launch_bounds__(256, 2) k_layer(int cur, int l, int N,
                                                  const float* __restrict__ bih,
                                                  const float* __restrict__ bhh) {
    extern __shared__ char smem[];
    uint32_t sb = smem_u32(smem);
    int tid = threadIdx.x, wid = tid >> 5, lane = tid & 31;
    const float* Xin  = cur ? d_xB : d_xA;
    float*       Xout = cur ? d_xA : d_xB;
    char* buf = smem + SM_BUF;

    // ---- load resident B (fp16), pitch BP ----
    {
        const int4* src = (const int4*)(&d_Bk[l][0][0]);
        for (int i = tid; i < 3072; i += 256) {
            int row = i / 48, cb = i % 48;
            *(int4*)(smem + SM_B + row * (BP * 2) + cb * 16) = src[i];
        }
    }

    // consumer setup
    uint32_t aoff = (uint32_t)(lane & 15) * (AP * 2) + ((lane >> 4) << 3) * 2;
    uint32_t boff = (uint32_t)(lane & 15) * (BP * 2);
    int wcol = wid * 48;
    int gID = lane >> 2, tig = lane & 3;
    int d0 = wid * 8 + 2 * tig;
    float bir0 = __ldg(&bih[d0]),        bir1 = __ldg(&bih[d0 + 1]);
    float biz0 = __ldg(&bih[64 + d0]),   biz1 = __ldg(&bih[64 + d0 + 1]);
    float bin0 = __ldg(&bih[128 + d0]),  bin1 = __ldg(&bih[128 + d0 + 1]);
    float bhr0 = __ldg(&bhh[d0]),        bhr1 = __ldg(&bhh[d0 + 1]);
    float bhz0 = __ldg(&bhh[64 + d0]),   bhz1 = __ldg(&bhh[64 + d0 + 1]);
    float bhn0 = __ldg(&bhh[128 + d0]),  bhn1 = __ldg(&bhh[128 + d0 + 1]);

    int ntiles = (N + 63) >> 6;
    for (int t = blockIdx.x; t < ntiles; t += gridDim.x) {
        int n0 = t << 6;
        __syncthreads();   // previous tile's MMA reads complete before overwrite

        // ---- phase 1: gather + fp16 convert, 8 warps x 8 nodes ----
        #pragma unroll 1
        for (int nn = 0; nn < 8; nn++) {
            int node = wid * 8 + nn;
            int gn = n0 + node;
            float2 sa = make_float2(0.f, 0.f);
            float2 xv = make_float2(0.f, 0.f);
            if (gn < N) {
                int o = d_off[gn], dg = d_indeg[gn];
                float2 a0 = make_float2(0.f, 0.f), a1 = make_float2(0.f, 0.f);
                float2 a2 = make_float2(0.f, 0.f), a3 = make_float2(0.f, 0.f);
                int e = 0;
                for (; e + 3 < dg; e += 4) {
                    int u0 = d_csrc[o + e],     u1 = d_csrc[o + e + 1];
                    int u2 = d_csrc[o + e + 2], u3 = d_csrc[o + e + 3];
                    float2 v0 = ((const float2*)(Xin + u0 * 64))[lane];
                    float2 v1 = ((const float2*)(Xin + u1 * 64))[lane];
                    float2 v2 = ((const float2*)(Xin + u2 * 64))[lane];
                    float2 v3 = ((const float2*)(Xin + u3 * 64))[lane];
                    a0.x += v0.x; a0.y += v0.y;
                    a1.x += v1.x; a1.y += v1.y;
                    a2.x += v2.x; a2.y += v2.y;
                    a3.x += v3.x; a3.y += v3.y;
                }
                for (; e < dg; e++) {
                    int u = d_csrc[o + e];
                    float2 v = ((const float2*)(Xin + u * 64))[lane];
                    a0.x += v.x; a0.y += v.y;
                }
                sa.x = (a0.x + a1.x) + (a2.x + a3.x);
                sa.y = (a0.y + a1.y) + (a2.y + a3.y);
                xv = ((const float2*)(Xin + gn * 64))[lane];
            }
            __half2 sh = __float22half2_rn(sa);
            float2 shf = __half22float2(sh);
            __half2 sl = __float22half2_rn(make_float2(sa.x - shf.x, sa.y - shf.y));
            __half2 xh = __float22half2_rn(xv);
            uint32_t off = (uint32_t)node * (AP * 2) + lane * 4;
            *(uint32_t*)(buf + OF_SHI + off) = *(uint32_t*)&sh;
            *(uint32_t*)(buf + OF_SLO + off) = *(uint32_t*)&sl;
            *(uint32_t*)(buf + OF_XHI + off) = *(uint32_t*)&xh;
        }
        __syncthreads();

        // ---- phase 2: MMA + register GRU (each warp: both 32-row chunks) ----
        uint32_t bufa = sb + SM_BUF;
        #pragma unroll
        for (int mi = 0; mi < 2; mi++) {
            int m0 = mi * 32;
            float c[2][6][4];
            #pragma unroll
            for (int mf = 0; mf < 2; mf++)
                #pragma unroll
                for (int j = 0; j < 6; j++)
                    #pragma unroll
                    for (int q = 0; q < 4; q++) c[mf][j][q] = 0.0f;

            #pragma unroll
            for (int ks = 0; ks < 4; ks++) {
                int k0 = ks * 16;
                uint32_t abase = (uint32_t)m0 * (AP * 2) + k0 * 2 + aoff;
                uint32_t sh[2][4], sl[2][4], xh[2][4];
                ldmA4(sh[0], bufa + OF_SHI + abase);
                ldmA4(sh[1], bufa + OF_SHI + abase + 16 * (AP * 2));
                ldmA4(sl[0], bufa + OF_SLO + abase);
                ldmA4(sl[1], bufa + OF_SLO + abase + 16 * (AP * 2));
                ldmA4(xh[0], bufa + OF_XHI + abase);
                ldmA4(xh[1], bufa + OF_XHI + abase + 16 * (AP * 2));
                #pragma unroll
                for (int j = 0; j < 6; j++) {
                    uint32_t bh[2];
                    uint32_t bbase = (uint32_t)k0 * (BP * 2) + (wcol + 8 * j) * 2 + boff;
                    ldmB2(bh, sb + SM_B + bbase);
                    if (j < 3) {
                        mma16816(c[0][j], sh[0], bh);
                        mma16816(c[1][j], sh[1], bh);
                        mma16816(c[0][j], sl[0], bh);
                        mma16816(c[1][j], sl[1], bh);
                    } else {
                        mma16816(c[0][j], xh[0], bh);
                        mma16816(c[1][j], xh[1], bh);
                    }
                }
            }

            // register GRU epilogue for this 32-node chunk
            #pragma unroll
            for (int mf = 0; mf < 2; mf++) {
                #pragma unroll
                for (int half = 0; half < 2; half++) {
                    int r = m0 + mf * 16 + gID + half * 8;
                    int node = n0 + r;
                    if (node < N) {
                        int q0 = half * 2, q1 = q0 + 1;
                        float2 xi = __ldg(((const float2*)(Xin + node * 64)) + (d0 >> 1));
                        float rr0 = sigf(c[mf][0][q0] + bir0 + c[mf][3][q0] + bhr0);
                        float zz0 = sigf(c[mf][1][q0] + biz0 + c[mf][4][q0] + bhz0);
                        float nn0 = tanhf(c[mf][2][q0] + bin0 + rr0 * (c[mf][5][q0] + bhn0));
                        float o0 = (1.0f - zz0) * nn0 + zz0 * xi.x;
                        float rr1 = sigf(c[mf][0][q1] + bir1 + c[mf][3][q1] + bhr1);
                        float zz1 = sigf(c[mf][1][q1] + biz1 + c[mf][4][q1] + bhz1);
                        float nn1 = tanhf(c[mf][2][q1] + bin1 + rr1 * (c[mf][5][q1] + bhn1));
                        float o1 = (1.0f - zz1) * nn1 + zz1 * xi.y;
                        ((float2*)(Xout + node * 64))[d0 >> 1] = make_float2(o0, o1);
                    }
                }
            }
        }
    }
}

// ---------------- segmented pooling (batch is sorted) ----------------
__global__ void k_pool2(int cur, int N) {
    __shared__ float red[256];
    const float* x = cur ? d_xB : d_xA;
    int g = blockIdx.x;
    int t = threadIdx.x;
    int d = t & 63, part = t >> 6;
    int s = d_gstart[g], e = d_gstart[g + 1];
    float acc = 0.0f;
    for (int n = s + part; n < e; n += 4) acc += x[n * D + d];
    red[t] = acc;
    __syncthreads();
    if (t < 64)
        d_pool[g * D + t] = red[t] + red[64 + t] + red[128 + t] + red[192 + t];
}

__global__ void k_mlp(const float* __restrict__ w1, const float* __restrict__ b1,
                      const float* __restrict__ w2, const float* __restrict__ b2,
                      const float* __restrict__ w3, const float* __restrict__ b3,
                      float* __restrict__ out) {
    __shared__ float h1[32], h2[16];
    int g = blockIdx.x, t = threadIdx.x;
    if (t < 32) {
        float s = b1[t];
        for (int k = 0; k < D; k++) s += d_pool[g * D + k] * w1[t * D + k];
        h1[t] = (s > 0.0f) ? s : expm1f(s);
    }
    __syncthreads();
    if (t < 16) {
        float s = b2[t];
        for (int k = 0; k < 32; k++) s += h1[k] * w2[t * 32 + k];
        h2[t] = (s > 0.0f) ? s : expm1f(s);
    }
    __syncthreads();
    if (t == 0) {
        float s = b3[0];
        for (int k = 0; k < 16; k++) s += h2[k] * w3[k];
        out[g] = s;
    }
}

// ---------------- launch ----------------
extern "C" void kernel_launch(void* const* d_in, const int* in_sizes, int n_in,
                              void* d_out, int out_size) {
    const float* convw = (const float*)d_in[0];
    const float* wih   = (const float*)d_in[1];
    const float* whh   = (const float*)d_in[2];
    const float* bih   = (const float*)d_in[3];
    const float* bhh   = (const float*)d_in[4];
    const float* fc1w  = (const float*)d_in[5];
    const float* fc1b  = (const float*)d_in[6];
    const float* fc2w  = (const float*)d_in[7];
    const float* fc2b  = (const float*)d_in[8];
    const float* fc3w  = (const float*)d_in[9];
    const float* fc3b  = (const float*)d_in[10];
    const int*   ei    = (const int*)d_in[11];
    const int*   batch = (const int*)d_in[12];

    int E = in_sizes[11] / 2;
    int N = in_sizes[12];
    int G = out_size;
    float* out = (float*)d_out;

    static int smem_set = 0;
    if (!smem_set) {
        cudaFuncSetAttribute(k_layer, cudaFuncAttributeMaxDynamicSharedMemorySize, SM_TOT);
        smem_set = 1;
    }

    int tb = 256;
    int gN    = (N + tb - 1) / tb;
    int gE    = (E + tb - 1) / tb;
    int gND   = (N * D + tb - 1) / tb;
    int nchunks = (N + 1023) >> 10;

    // CSR build + graph ranges (parallel 3-phase scan)
    k_init<<<gN, tb>>>(N, G);
    k_count<<<gE, tb>>>(ei, batch, E, N);
    k_scanA<<<nchunks, 256>>>(N);
    k_scanB<<<1, 1>>>(nchunks);
    k_scanC<<<nchunks, 1024>>>(N);
    k_fill<<<gE, tb>>>(ei, E);
    k_gfix<<<1, 1>>>(G, N);

    // analytic layers 1+2 and B packing
    k_const<<<1, 192>>>(convw, wih, whh, bih, bhh);
    k_layer2<<<gND, tb>>>(bih + C3, N);           // writes d_xA (cur=0)
    k_bprep<<<(73728 + tb - 1) / tb, tb>>>(convw, wih, whh);

    // layers 3..5: fused gather + HMMA + GRU, 2 blocks/SM phase overlap, ping-pong
    int cur = 0;
    for (int l = 0; l < 3; l++) {
        int lg = l + 2;
        k_layer<<<296, 256, SM_TOT>>>(cur, l, N, bih + lg * C3, bhh + lg * C3);
        cur ^= 1;
    }

    // pooling + MLP head
    k_pool2<<<G, 256>>>(cur, N);
    k_mlp<<<G, 64>>>(fc1w, fc1b, fc2w, fc2b, fc3w, fc3b, out);
}

// round 17
// speedup vs baseline: 2.0215x; 1.0333x over previous
#include <cuda_runtime.h>
#include <cuda_fp16.h>
#include <math.h>
#include <stdint.h>

#define D   64
#define C3  192
#define MAXN 100352
#define MAXE 1600064

// ---------------- device scratch (static, no allocation) ----------------
__device__ float d_xA[MAXN * D];
__device__ float d_xB[MAXN * D];
__device__ int   d_indeg[MAXN];
__device__ int   d_off  [MAXN];
__device__ int   d_cur  [MAXN];
__device__ int   d_csrc [MAXE];
__device__ int   d_csum [128];
// Packed fp16 B per layer l=0..2 (global 2..4): [k=0..63][col'=0..383]
// col' = w*48 + j*8 + t : warp w owns dims 8w..8w+7; j=0..2 gi gates (r,z,n), j=3..5 gh gates
__device__ __align__(16) __half d_Bk[3][64][384];
__device__ float d_q[C3], d_p2[C3], d_x1row[D];
__device__ float d_pool[64 * D];
__device__ int   d_gstart[66];

__device__ __forceinline__ float sigf(float x) { return 1.0f / (1.0f + expf(-x)); }

__device__ __forceinline__ uint32_t smem_u32(const void* p) {
    uint32_t a;
    asm("{ .reg .u64 t; cvta.to.shared.u64 t, %1; cvt.u32.u64 %0, t; }" : "=r"(a) : "l"(p));
    return a;
}
__device__ __forceinline__ void ldmA4(uint32_t a[4], uint32_t addr) {
    asm volatile("ldmatrix.sync.aligned.m8n8.x4.shared.b16 {%0,%1,%2,%3}, [%4];"
                 : "=r"(a[0]), "=r"(a[1]), "=r"(a[2]), "=r"(a[3]) : "r"(addr));
}
__device__ __forceinline__ void ldmB2(uint32_t b[2], uint32_t addr) {
    asm volatile("ldmatrix.sync.aligned.m8n8.x2.trans.shared.b16 {%0,%1}, [%2];"
                 : "=r"(b[0]), "=r"(b[1]) : "r"(addr));
}
__device__ __forceinline__ void mma16816(float c[4], const uint32_t a[4], const uint32_t b[2]) {
    asm volatile("mma.sync.aligned.m16n8k16.row.col.f32.f16.f16.f32 "
                 "{%0,%1,%2,%3}, {%4,%5,%6,%7}, {%8,%9}, {%0,%1,%2,%3};"
                 : "+f"(c[0]), "+f"(c[1]), "+f"(c[2]), "+f"(c[3])
                 : "r"(a[0]), "r"(a[1]), "r"(a[2]), "r"(a[3]), "r"(b[0]), "r"(b[1]));
}

// ---------------- CSR build ----------------
__global__ void k_init(int N, int G) {
    int i = blockIdx.x * blockDim.x + threadIdx.x;
    if (i < N) d_indeg[i] = 0;
    if (i <= G + 1) d_gstart[i] = N;
}

// edge counting + graph boundary detection (batch is sorted)
__global__ void k_count(const int* __restrict__ ei, const int* __restrict__ batch,
                        int E, int N) {
    int i = blockIdx.x * blockDim.x + threadIdx.x;
    if (i < E) atomicAdd(&d_indeg[ei[E + i]], 1);
    if (i < N) {
        if (i == 0) d_gstart[batch[0]] = 0;
        else if (batch[i] != batch[i - 1]) d_gstart[batch[i]] = i;
    }
}

// ---- parallel 3-phase exclusive scan over indegree ----
__global__ void k_scanA(int N) {
    __shared__ int sm[256];
    int c = blockIdx.x, t = threadIdx.x;
    int base = c << 10;
    int s = 0;
    #pragma unroll
    for (int j = 0; j < 4; j++) {
        int i = base + t + j * 256;
        if (i < N) s += d_indeg[i];
    }
    sm[t] = s;
    __syncthreads();
    for (int off = 128; off > 0; off >>= 1) {
        if (t < off) sm[t] += sm[t + off];
        __syncthreads();
    }
    if (t == 0) d_csum[c] = sm[0];
}

__global__ void k_scanB(int nchunks) {
    int run = 0;
    for (int c = 0; c < nchunks; c++) {
        int v = d_csum[c];
        d_csum[c] = run;
        run += v;
    }
}

__global__ void k_scanC(int N) {
    __shared__ int sm[1024];
    int c = blockIdx.x, t = threadIdx.x;
    int i = (c << 10) + t;
    int v = (i < N) ? d_indeg[i] : 0;
    sm[t] = v;
    __syncthreads();
    for (int off = 1; off < 1024; off <<= 1) {
        int u = (t >= off) ? sm[t - off] : 0;
        __syncthreads();
        sm[t] += u;
        __syncthreads();
    }
    if (i < N) {
        int excl = d_csum[c] + sm[t] - v;
        d_off[i] = excl;
        d_cur[i] = excl;
    }
}

__global__ void k_fill(const int* __restrict__ ei, int E) {
    int i = blockIdx.x * blockDim.x + threadIdx.x;
    if (i < E) {
        int s = ei[i];
        int d = ei[E + i];
        int p = atomicAdd(&d_cur[d], 1);
        d_csrc[p] = s;
    }
}

__global__ void k_gfix(int G, int N) {
    d_gstart[G] = N;
    for (int g = G - 1; g >= 0; g--)
        if (d_gstart[g] > d_gstart[g + 1]) d_gstart[g] = d_gstart[g + 1];
}

// ---------------- layers 1+2 analytic shortcuts ----------------
__global__ void k_const(const float* __restrict__ convw,
                        const float* __restrict__ wih,
                        const float* __restrict__ whh,
                        const float* __restrict__ bih,
                        const float* __restrict__ bhh) {
    __shared__ float x1[D], m2[D];
    int t = threadIdx.x;
    if (t < D) {
        float r = sigf(bih[t] + bhh[t]);
        float z = sigf(bih[64 + t] + bhh[64 + t]);
        float n = tanhf(bih[128 + t] + r * bhh[128 + t]);
        x1[t] = (1.0f - z) * n;
    }
    __syncthreads();
    if (t < D) {
        const float* w1 = convw + 1 * D * D;
        float s = 0.0f;
        for (int k = 0; k < D; k++) s += x1[k] * w1[k * D + t];
        m2[t] = s;
        d_x1row[t] = x1[t];
    }
    __syncthreads();
    if (t < C3) {
        const float* wih1 = wih + 1 * C3 * D;
        const float* whh1 = whh + 1 * C3 * D;
        const float* bhh1 = bhh + 1 * C3;
        float sq = 0.0f, sp = 0.0f;
        for (int j = 0; j < D; j++) {
            sq += m2[j] * wih1[t * D + j];
            sp += x1[j] * whh1[t * D + j];
        }
        d_q[t]  = sq;
        d_p2[t] = sp + bhh1[t];
    }
}

__global__ void k_layer2(const float* __restrict__ bih1, int N) {
    int idx = blockIdx.x * blockDim.x + threadIdx.x;
    if (idx >= N * D) return;
    int v = idx >> 6, d = idx & 63;
    float deg = (float)d_indeg[v];
    float r = sigf(deg * d_q[d]       + bih1[d]       + d_p2[d]);
    float z = sigf(deg * d_q[64 + d]  + bih1[64 + d]  + d_p2[64 + d]);
    float n = tanhf(deg * d_q[128 + d] + bih1[128 + d] + r * d_p2[128 + d]);
    d_xA[idx] = (1.0f - z) * n + z * d_x1row[d];
}

// ---------------- pre-pack fp16 B, gate-interleaved cols ----------------
__global__ void k_bprep(const float* __restrict__ convw,
                        const float* __restrict__ wih,
                        const float* __restrict__ whh) {
    int idx = blockIdx.x * blockDim.x + threadIdx.x;  // 3*2*192*64
    if (idx >= 73728) return;
    int l0 = idx / 24576;
    int rem = idx % 24576;
    int m = rem / 12288;
    int rem2 = rem % 12288;
    int c = rem2 >> 6;      // 0..191 (gate*64 + d)
    int k = rem2 & 63;
    int lg = l0 + 2;
    float val;
    if (m == 0) {
        const float* w  = convw + lg * D * D + k * D;
        const float* wi = wih   + lg * C3 * D + c * D;
        float s = 0.0f;
        for (int j = 0; j < D; j++) s += w[j] * wi[j];
        val = s;
    } else {
        val = whh[lg * C3 * D + c * D + k];
    }
    int gate = c >> 6, d = c & 63;
    int w8 = d >> 3, t = d & 7;
    int jj = (m == 0) ? gate : gate + 3;
    int col = w8 * 48 + jj * 8 + t;
    d_Bk[l0][k][col] = __float2half_rn(val);
}

// ---------------- fused layer: gather phase + HMMA+GRU phase ----------------
// 256 threads = 8 warps, 64-node tiles, 2 blocks/SM for cross-block phase overlap.
// Warp w owns dims 8w..8w+7 (cols w*48..+47), both 32-row chunks.
// A: S = Sh single term, X = Xh single term (rel_err 3.04e-4 measured R15).
#define BP 392            // B smem pitch (halves): 784B
#define AP 72             // A smem pitch (halves): 144B
#define SM_B    0
#define SM_BUF  50176
#define OF_SHI 0
#define OF_XHI 9216
#define SM_TOT  (50176 + 18432)

__global__ void __launch_bounds__(256, 2) k_layer(int cur, int l, int N,
                                                  const float* __restrict__ bih,
                                                  const float* __restrict__ bhh) {
    extern __shared__ char smem[];
    uint32_t sb = smem_u32(smem);
    int tid = threadIdx.x, wid = tid >> 5, lane = tid & 31;
    const float* Xin  = cur ? d_xB : d_xA;
    float*       Xout = cur ? d_xA : d_xB;
    char* buf = smem + SM_BUF;

    // ---- load resident B (fp16), pitch BP ----
    {
        const int4* src = (const int4*)(&d_Bk[l][0][0]);
        for (int i = tid; i < 3072; i += 256) {
            int row = i / 48, cb = i % 48;
            *(int4*)(smem + SM_B + row * (BP * 2) + cb * 16) = src[i];
        }
    }

    // consumer setup
    uint32_t aoff = (uint32_t)(lane & 15) * (AP * 2) + ((lane >> 4) << 3) * 2;
    uint32_t boff = (uint32_t)(lane & 15) * (BP * 2);
    int wcol = wid * 48;
    int gID = lane >> 2, tig = lane & 3;
    int d0 = wid * 8 + 2 * tig;
    float bir0 = __ldg(&bih[d0]),        bir1 = __ldg(&bih[d0 + 1]);
    float biz0 = __ldg(&bih[64 + d0]),   biz1 = __ldg(&bih[64 + d0 + 1]);
    float bin0 = __ldg(&bih[128 + d0]),  bin1 = __ldg(&bih[128 + d0 + 1]);
    float bhr0 = __ldg(&bhh[d0]),        bhr1 = __ldg(&bhh[d0 + 1]);
    float bhz0 = __ldg(&bhh[64 + d0]),   bhz1 = __ldg(&bhh[64 + d0 + 1]);
    float bhn0 = __ldg(&bhh[128 + d0]),  bhn1 = __ldg(&bhh[128 + d0 + 1]);

    int ntiles = (N + 63) >> 6;
    for (int t = blockIdx.x; t < ntiles; t += gridDim.x) {
        int n0 = t << 6;
        __syncthreads();   // previous tile's MMA reads complete before overwrite

        // ---- phase 1: gather + fp16 convert, 8 warps x 8 nodes ----
        #pragma unroll 1
        for (int nn = 0; nn < 8; nn++) {
            int node = wid * 8 + nn;
            int gn = n0 + node;
            float2 sa = make_float2(0.f, 0.f);
            float2 xv = make_float2(0.f, 0.f);
            if (gn < N) {
                int o = d_off[gn], dg = d_indeg[gn];
                float2 a0 = make_float2(0.f, 0.f), a1 = make_float2(0.f, 0.f);
                float2 a2 = make_float2(0.f, 0.f), a3 = make_float2(0.f, 0.f);
                int e = 0;
                for (; e + 3 < dg; e += 4) {
                    int u0 = d_csrc[o + e],     u1 = d_csrc[o + e + 1];
                    int u2 = d_csrc[o + e + 2], u3 = d_csrc[o + e + 3];
                    float2 v0 = ((const float2*)(Xin + u0 * 64))[lane];
                    float2 v1 = ((const float2*)(Xin + u1 * 64))[lane];
                    float2 v2 = ((const float2*)(Xin + u2 * 64))[lane];
                    float2 v3 = ((const float2*)(Xin + u3 * 64))[lane];
                    a0.x += v0.x; a0.y += v0.y;
                    a1.x += v1.x; a1.y += v1.y;
                    a2.x += v2.x; a2.y += v2.y;
                    a3.x += v3.x; a3.y += v3.y;
                }
                for (; e < dg; e++) {
                    int u = d_csrc[o + e];
                    float2 v = ((const float2*)(Xin + u * 64))[lane];
                    a0.x += v.x; a0.y += v.y;
                }
                sa.x = (a0.x + a1.x) + (a2.x + a3.x);
                sa.y = (a0.y + a1.y) + (a2.y + a3.y);
                xv = ((const float2*)(Xin + gn * 64))[lane];
            }
            __half2 sh = __float22half2_rn(sa);
            __half2 xh = __float22half2_rn(xv);
            uint32_t off = (uint32_t)node * (AP * 2) + lane * 4;
            *(uint32_t*)(buf + OF_SHI + off) = *(uint32_t*)&sh;
            *(uint32_t*)(buf + OF_XHI + off) = *(uint32_t*)&xh;
        }
        __syncthreads();

        // ---- phase 2: MMA + register GRU (each warp: both 32-row chunks) ----
        uint32_t bufa = sb + SM_BUF;
        #pragma unroll
        for (int mi = 0; mi < 2; mi++) {
            int m0 = mi * 32;
            float c[2][6][4];
            #pragma unroll
            for (int mf = 0; mf < 2; mf++)
                #pragma unroll
                for (int j = 0; j < 6; j++)
                    #pragma unroll
                    for (int q = 0; q < 4; q++) c[mf][j][q] = 0.0f;

            #pragma unroll
            for (int ks = 0; ks < 4; ks++) {
                int k0 = ks * 16;
                uint32_t abase = (uint32_t)m0 * (AP * 2) + k0 * 2 + aoff;
                uint32_t sh[2][4], xh[2][4];
                ldmA4(sh[0], bufa + OF_SHI + abase);
                ldmA4(sh[1], bufa + OF_SHI + abase + 16 * (AP * 2));
                ldmA4(xh[0], bufa + OF_XHI + abase);
                ldmA4(xh[1], bufa + OF_XHI + abase + 16 * (AP * 2));
                #pragma unroll
                for (int j = 0; j < 6; j++) {
                    uint32_t bh[2];
                    uint32_t bbase = (uint32_t)k0 * (BP * 2) + (wcol + 8 * j) * 2 + boff;
                    ldmB2(bh, sb + SM_B + bbase);
                    if (j < 3) {
                        mma16816(c[0][j], sh[0], bh);
                        mma16816(c[1][j], sh[1], bh);
                    } else {
                        mma16816(c[0][j], xh[0], bh);
                        mma16816(c[1][j], xh[1], bh);
                    }
                }
            }

            // register GRU epilogue for this 32-node chunk
            #pragma unroll
            for (int mf = 0; mf < 2; mf++) {
                #pragma unroll
                for (int half = 0; half < 2; half++) {
                    int r = m0 + mf * 16 + gID + half * 8;
                    int node = n0 + r;
                    if (node < N) {
                        int q0 = half * 2, q1 = q0 + 1;
                        float2 xi = __ldg(((const float2*)(Xin + node * 64)) + (d0 >> 1));
                        float rr0 = sigf(c[mf][0][q0] + bir0 + c[mf][3][q0] + bhr0);
                        float zz0 = sigf(c[mf][1][q0] + biz0 + c[mf][4][q0] + bhz0);
                        float nn0 = tanhf(c[mf][2][q0] + bin0 + rr0 * (c[mf][5][q0] + bhn0));
                        float o0 = (1.0f - zz0) * nn0 + zz0 * xi.x;
                        float rr1 = sigf(c[mf][0][q1] + bir1 + c[mf][3][q1] + bhr1);
                        float zz1 = sigf(c[mf][1][q1] + biz1 + c[mf][4][q1] + bhz1);
                        float nn1 = tanhf(c[mf][2][q1] + bin1 + rr1 * (c[mf][5][q1] + bhn1));
                        float o1 = (1.0f - zz1) * nn1 + zz1 * xi.y;
                        ((float2*)(Xout + node * 64))[d0 >> 1] = make_float2(o0, o1);
                    }
                }
            }
        }
    }
}

// ---------------- segmented pooling (batch is sorted) ----------------
__global__ void k_pool2(int cur, int N) {
    __shared__ float red[256];
    const float* x = cur ? d_xB : d_xA;
    int g = blockIdx.x;
    int t = threadIdx.x;
    int d = t & 63, part = t >> 6;
    int s = d_gstart[g], e = d_gstart[g + 1];
    float acc = 0.0f;
    for (int n = s + part; n < e; n += 4) acc += x[n * D + d];
    red[t] = acc;
    __syncthreads();
    if (t < 64)
        d_pool[g * D + t] = red[t] + red[64 + t] + red[128 + t] + red[192 + t];
}

__global__ void k_mlp(const float* __restrict__ w1, const float* __restrict__ b1,
                      const float* __restrict__ w2, const float* __restrict__ b2,
                      const float* __restrict__ w3, const float* __restrict__ b3,
                      float* __restrict__ out) {
    __shared__ float h1[32], h2[16];
    int g = blockIdx.x, t = threadIdx.x;
    if (t < 32) {
        float s = b1[t];
        for (int k = 0; k < D; k++) s += d_pool[g * D + k] * w1[t * D + k];
        h1[t] = (s > 0.0f) ? s : expm1f(s);
    }
    __syncthreads();
    if (t < 16) {
        float s = b2[t];
        for (int k = 0; k < 32; k++) s += h1[k] * w2[t * 32 + k];
        h2[t] = (s > 0.0f) ? s : expm1f(s);
    }
    __syncthreads();
    if (t == 0) {
        float s = b3[0];
        for (int k = 0; k < 16; k++) s += h2[k] * w3[k];
        out[g] = s;
    }
}

// ---------------- launch ----------------
extern "C" void kernel_launch(void* const* d_in, const int* in_sizes, int n_in,
                              void* d_out, int out_size) {
    const float* convw = (const float*)d_in[0];
    const float* wih   = (const float*)d_in[1];
    const float* whh   = (const float*)d_in[2];
    const float* bih   = (const float*)d_in[3];
    const float* bhh   = (const float*)d_in[4];
    const float* fc1w  = (const float*)d_in[5];
    const float* fc1b  = (const float*)d_in[6];
    const float* fc2w  = (const float*)d_in[7];
    const float* fc2b  = (const float*)d_in[8];
    const float* fc3w  = (const float*)d_in[9];
    const float* fc3b  = (const float*)d_in[10];
    const int*   ei    = (const int*)d_in[11];
    const int*   batch = (const int*)d_in[12];

    int E = in_sizes[11] / 2;
    int N = in_sizes[12];
    int G = out_size;
    float* out = (float*)d_out;

    static int smem_set = 0;
    if (!smem_set) {
        cudaFuncSetAttribute(k_layer, cudaFuncAttributeMaxDynamicSharedMemorySize, SM_TOT);
        smem_set = 1;
    }

    int tb = 256;
    int gN    = (N + tb - 1) / tb;
    int gE    = (E + tb - 1) / tb;
    int gND   = (N * D + tb - 1) / tb;
    int nchunks = (N + 1023) >> 10;

    // CSR build + graph ranges (parallel 3-phase scan)
    k_init<<<gN, tb>>>(N, G);
    k_count<<<gE, tb>>>(ei, batch, E, N);
    k_scanA<<<nchunks, 256>>>(N);
    k_scanB<<<1, 1>>>(nchunks);
    k_scanC<<<nchunks, 1024>>>(N);
    k_fill<<<gE, tb>>>(ei, E);
    k_gfix<<<1, 1>>>(G, N);

    // analytic layers 1+2 and B packing
    k_const<<<1, 192>>>(convw, wih, whh, bih, bhh);
    k_layer2<<<gND, tb>>>(bih + C3, N);           // writes d_xA (cur=0)
    k_bprep<<<(73728 + tb - 1) / tb, tb>>>(convw, wih, whh);

    // layers 3..5: fused gather + HMMA + GRU, 2 blocks/SM phase overlap, ping-pong
    int cur = 0;
    for (int l = 0; l < 3; l++) {
        int lg = l + 2;
        k_layer<<<296, 256, SM_TOT>>>(cur, l, N, bih + lg * C3, bhh + lg * C3);
        cur ^= 1;
    }

    // pooling + MLP head
    k_pool2<<<G, 256>>>(cur, N);
    k_mlp<<<G, 64>>>(fc1w, fc1b, fc2w, fc2b, fc3w, fc3b, out);
}